// round 13
// baseline (speedup 1.0000x reference)
#include <cuda_runtime.h>
#include <cuda_bf16.h>
#include <cstdint>

#define T_SEQ 512
#define BATCH 1024
#define DIN   32
#define HDIM  64
#define G     256     // 4*H gate rows
#define NB    8       // batches per CTA
#define NTHR  256     // A: warps 0-3 (layer 0 + x-part), B: warps 4-7 (layer 1)
#define SW0_S 68      // Whh0 row stride: 68%32=4 -> 2-wf LDS.128 at 16 distinct rows
#define SW1_S 132     // [Wih1|Whh1] row stride: 132%32=4 -> same
#define XP_S  9       // x-part exchange stride: coprime 32 -> conflict-free

// smem floats: sW0 17408 | sW1 33792 | xp 2*2304 | xsb 2*256 | h0T 1024 | h1T 512
//            = 57856 fl = 231424 B  (<= 232448 B cap)
#define SMEM_FLOATS (G*SW0_S + G*SW1_S + 2*(G*XP_S) + 2*(NB*DIN) + 2*(NB*64) + NB*64)

__device__ __forceinline__ unsigned long long pack2(float lo, float hi) {
    unsigned long long r;
    asm("mov.b64 %0, {%1,%2};" : "=l"(r) : "f"(lo), "f"(hi));
    return r;
}
__device__ __forceinline__ void fma2(unsigned long long& d,
                                     unsigned long long a, unsigned long long b) {
    asm("fma.rn.f32x2 %0, %1, %2, %0;" : "+l"(d) : "l"(a), "l"(b));
}
__device__ __forceinline__ float hsum2(unsigned long long v) {
    float lo, hi;
    asm("mov.b64 {%0,%1}, %2;" : "=f"(lo), "=f"(hi) : "l"(v));
    return lo + hi;
}
__device__ __forceinline__ float sigmoid_fast(float x) {
    return __fdividef(1.0f, 1.0f + __expf(-x));
}
__device__ __forceinline__ float tanh_fast(float x) {
    return 1.0f - __fdividef(2.0f, __expf(2.0f * x) + 1.0f);
}
__device__ __forceinline__ void bar_sync(int id, int cnt) {
    asm volatile("bar.sync %0, %1;" :: "r"(id), "r"(cnt) : "memory");
}
__device__ __forceinline__ void bar_arrive(int id, int cnt) {
    asm volatile("bar.arrive %0, %1;" :: "r"(id), "r"(cnt) : "memory");
}

extern __shared__ float smem[];

__global__ void __launch_bounds__(NTHR, 1)
lstm_return_kernel(const float* __restrict__ x,
                   const float* __restrict__ Wih0, const float* __restrict__ Whh0,
                   const float* __restrict__ bih0, const float* __restrict__ bhh0,
                   const float* __restrict__ Wih1, const float* __restrict__ Whh1,
                   const float* __restrict__ bih1, const float* __restrict__ bhh1,
                   const float* __restrict__ W1,   const float* __restrict__ b1,
                   const float* __restrict__ W2,   const float* __restrict__ b2,
                   float* __restrict__ out)
{
    float* sW0 = smem;                 // [256][68]  Whh0
    float* sW1 = sW0 + G * SW0_S;      // [256][132] [Wih1|Whh1]
    float* xp  = sW1 + G * SW1_S;      // [2][256][9] x-part (incl. bias0), dbl-buf
    float* xsb = xp  + 2 * G * XP_S;   // [2][8][32]  x staging, dbl-buf
    float* h0T = xsb + 2 * NB * DIN;   // [2][16][8][4] h0 transposed, dbl-buf
    float* h1T = h0T + 2 * 512;        // [16][8][4]    h1 transposed

    const int tid   = threadIdx.x;
    const int l     = tid & 31;
    const bool grpA = (tid < 128);
    const int gw    = (tid >> 5) & 3;       // warp index within group
    const int rq    = gw * 16 + (l & 15);   // owned unit (rows rq+64m, m=0..3)
    const int bg    = l >> 4;               // batch half
    const int bbase = blockIdx.x * NB;

    // ---- stage weights ----
    for (int i = tid; i < G * HDIM; i += NTHR) {
        int r = i >> 6, c = i & 63;
        sW0[r * SW0_S + c]        = Whh0[i];
        sW1[r * SW1_S + c]        = Wih1[i];
        sW1[r * SW1_S + HDIM + c] = Whh1[i];
    }
    for (int i = tid; i < 3 * 512; i += NTHR) h0T[i] = 0.0f;   // h0T + h1T

    // ---- A: Wih0 row-pair (jx, jx+128) in registers, packed f32x2 ----
    const int jx = tid;   // valid for grpA (tid<128)
    unsigned long long wx0[16], wx1[16];
#pragma unroll
    for (int k = 0; k < 16; k++) {
        int r0 = jx * DIN + 2 * k, r1 = (jx + 128) * DIN + 2 * k;
        wx0[k] = grpA ? pack2(Wih0[r0], Wih0[r0 + 1]) : 0ull;
        wx1[k] = grpA ? pack2(Wih0[r1], Wih0[r1 + 1]) : 0ull;
    }
    float bxa = 0.f, bxb = 0.f;
    if (grpA) { bxa = bih0[jx] + bhh0[jx]; bxb = bih0[jx + 128] + bhh0[jx + 128]; }

    float bs1[4];
#pragma unroll
    for (int m = 0; m < 4; m++)
        bs1[m] = grpA ? 0.0f : (bih1[rq + 64 * m] + bhh1[rq + 64 * m]);

    float cst[4] = {0.f, 0.f, 0.f, 0.f};

    // x staging (A): thread -> (batch xb, channels xc, xc+1)
    const int xb = tid >> 4, xc = (tid & 15) * 2;
    const float* xptr = x + ((size_t)(bbase + (xb & 7)) * T_SEQ) * DIN + xc;
    float2 xcur = make_float2(0.f, 0.f);
    if (grpA) {
        *(float2*)(xsb + 0 * 256 + xb * DIN + xc) = *(const float2*)(xptr);        // x(0)
        *(float2*)(xsb + 1 * 256 + xb * DIN + xc) = *(const float2*)(xptr + DIN);  // x(1)
        xcur = *(const float2*)(xptr + 2 * DIN);                                   // x(2)
    }

    const int wr0 = rq * SW0_S, wr1 = rq * SW1_S;

    __syncthreads();   // weights, zeros, xsb visible

    if (grpA) {
        // helper: compute x-part for buffer `buf` -> xp[buf]
        auto xpart = [&](int buf) {
            const float* xsp = xsb + buf * 256;
            float* xpd = xp + buf * (G * XP_S);
            unsigned long long a0[NB], a1[NB];
#pragma unroll
            for (int b = 0; b < NB; b++) { a0[b] = pack2(bxa, 0.f); a1[b] = pack2(bxb, 0.f); }
#pragma unroll
            for (int kc = 0; kc < 8; kc++) {
                const unsigned long long u0 = wx0[2*kc], u1 = wx0[2*kc+1];
                const unsigned long long v0 = wx1[2*kc], v1 = wx1[2*kc+1];
#pragma unroll
                for (int b = 0; b < NB; b++) {
                    ulonglong2 iv = *(const ulonglong2*)(xsp + b * DIN + 4 * kc);
                    fma2(a0[b], u0, iv.x); fma2(a0[b], u1, iv.y);
                    fma2(a1[b], v0, iv.x); fma2(a1[b], v1, iv.y);
                }
            }
#pragma unroll
            for (int b = 0; b < NB; b++) {
                xpd[jx * XP_S + b]         = hsum2(a0[b]);
                xpd[(jx + 128) * XP_S + b] = hsum2(a1[b]);
            }
        };

        xpart(0);                 // xp[0] = x-part(t=0)
        bar_sync(5, 128);         // xp[0] visible within A

        // =========================== GROUP A: layer 0 ===========================
        for (int t = 0; t < T_SEQ; t++) {
            const int p = t & 1;
            // ---- quad GEMV(t): acc init from xp[p], h0(t-1) from h0T[p^1] ----
            const float* xpc = xp + p * (G * XP_S);
            unsigned long long acc[16];
#pragma unroll
            for (int m = 0; m < 4; m++)
#pragma unroll
                for (int q = 0; q < 4; q++)
                    acc[m * 4 + q] = pack2(xpc[(rq + 64 * m) * XP_S + bg * 4 + q], 0.f);
            const float* h0p = h0T + (p ^ 1) * 512;
#pragma unroll
            for (int kc = 0; kc < 16; kc++) {
                ulonglong2 wv0 = *(const ulonglong2*)(sW0 + wr0 +   0 * SW0_S + 4 * kc);
                ulonglong2 wv1 = *(const ulonglong2*)(sW0 + wr0 +  64 * SW0_S + 4 * kc);
                ulonglong2 wv2 = *(const ulonglong2*)(sW0 + wr0 + 128 * SW0_S + 4 * kc);
                ulonglong2 wv3 = *(const ulonglong2*)(sW0 + wr0 + 192 * SW0_S + 4 * kc);
#pragma unroll
                for (int q = 0; q < 4; q++) {
                    ulonglong2 iv = *(const ulonglong2*)(h0p + kc * 32 + (bg * 4 + q) * 4);
                    fma2(acc[0 * 4 + q], wv0.x, iv.x); fma2(acc[0 * 4 + q], wv0.y, iv.y);
                    fma2(acc[1 * 4 + q], wv1.x, iv.x); fma2(acc[1 * 4 + q], wv1.y, iv.y);
                    fma2(acc[2 * 4 + q], wv2.x, iv.x); fma2(acc[2 * 4 + q], wv2.y, iv.y);
                    fma2(acc[3 * 4 + q], wv3.x, iv.x); fma2(acc[3 * 4 + q], wv3.y, iv.y);
                }
            }
            if (t >= 2) bar_sync(3 + p, NTHR);   // h0T[p] free (B consumed t-2)
            // ---- activations + cell + h0 write ----
            float* h0c = h0T + p * 512;
#pragma unroll
            for (int q = 0; q < 4; q++) {
                float i_ = sigmoid_fast(hsum2(acc[0 * 4 + q]));
                float f_ = sigmoid_fast(hsum2(acc[1 * 4 + q]));
                float g_ = tanh_fast(hsum2(acc[2 * 4 + q]));
                float o_ = sigmoid_fast(hsum2(acc[3 * 4 + q]));
                cst[q] = f_ * cst[q] + i_ * g_;
                float h = o_ * tanh_fast(cst[q]);
                h0c[(rq >> 2) * 32 + (bg * 4 + q) * 4 + (rq & 3)] = h;
            }
            bar_arrive(1 + p, NTHR);             // h0(t) ready for B

            // stage x(t+2) into xsb[p] (its old contents consumed at t-1)
            if (t + 2 < T_SEQ) {
                *(float2*)(xsb + p * 256 + xb * DIN + xc) = xcur;
                if (t + 3 < T_SEQ) xcur = *(const float2*)(xptr + (size_t)(t + 3) * DIN);
            }
            // x-part for step t+1 from xsb[p^1] -> xp[p^1]
            if (t + 1 < T_SEQ) xpart(p ^ 1);
            bar_sync(5, 128);                    // xp, xsb, h0T[p] visible within A
        }
    } else {
        // =========================== GROUP B: layer 1 ===========================
        for (int t = 0; t < T_SEQ; t++) {
            const int p = t & 1;
            unsigned long long acc[16];
#pragma unroll
            for (int m = 0; m < 4; m++)
#pragma unroll
                for (int q = 0; q < 4; q++) acc[m * 4 + q] = pack2(bs1[m], 0.0f);
            // part 1 (independent of A): h1(t-1) @ Whh1^T  [h1T ordered by bar 7]
#pragma unroll
            for (int kc = 0; kc < 16; kc++) {
                ulonglong2 wv0 = *(const ulonglong2*)(sW1 + wr1 +   0 * SW1_S + 64 + 4 * kc);
                ulonglong2 wv1 = *(const ulonglong2*)(sW1 + wr1 +  64 * SW1_S + 64 + 4 * kc);
                ulonglong2 wv2 = *(const ulonglong2*)(sW1 + wr1 + 128 * SW1_S + 64 + 4 * kc);
                ulonglong2 wv3 = *(const ulonglong2*)(sW1 + wr1 + 192 * SW1_S + 64 + 4 * kc);
#pragma unroll
                for (int q = 0; q < 4; q++) {
                    ulonglong2 iv = *(const ulonglong2*)(h1T + kc * 32 + (bg * 4 + q) * 4);
                    fma2(acc[0 * 4 + q], wv0.x, iv.x); fma2(acc[0 * 4 + q], wv0.y, iv.y);
                    fma2(acc[1 * 4 + q], wv1.x, iv.x); fma2(acc[1 * 4 + q], wv1.y, iv.y);
                    fma2(acc[2 * 4 + q], wv2.x, iv.x); fma2(acc[2 * 4 + q], wv2.y, iv.y);
                    fma2(acc[3 * 4 + q], wv3.x, iv.x); fma2(acc[3 * 4 + q], wv3.y, iv.y);
                }
            }
            bar_sync(1 + p, NTHR);               // wait h0(t)
            const float* h0p = h0T + p * 512;
            // part 2: h0(t) @ Wih1^T
#pragma unroll
            for (int kc = 0; kc < 16; kc++) {
                ulonglong2 wv0 = *(const ulonglong2*)(sW1 + wr1 +   0 * SW1_S + 4 * kc);
                ulonglong2 wv1 = *(const ulonglong2*)(sW1 + wr1 +  64 * SW1_S + 4 * kc);
                ulonglong2 wv2 = *(const ulonglong2*)(sW1 + wr1 + 128 * SW1_S + 4 * kc);
                ulonglong2 wv3 = *(const ulonglong2*)(sW1 + wr1 + 192 * SW1_S + 4 * kc);
#pragma unroll
                for (int q = 0; q < 4; q++) {
                    ulonglong2 iv = *(const ulonglong2*)(h0p + kc * 32 + (bg * 4 + q) * 4);
                    fma2(acc[0 * 4 + q], wv0.x, iv.x); fma2(acc[0 * 4 + q], wv0.y, iv.y);
                    fma2(acc[1 * 4 + q], wv1.x, iv.x); fma2(acc[1 * 4 + q], wv1.y, iv.y);
                    fma2(acc[2 * 4 + q], wv2.x, iv.x); fma2(acc[2 * 4 + q], wv2.y, iv.y);
                    fma2(acc[3 * 4 + q], wv3.x, iv.x); fma2(acc[3 * 4 + q], wv3.y, iv.y);
                }
            }
            bar_arrive(3 + p, NTHR);             // h0T[p] consumed
            // activations + cell + h1 write
#pragma unroll
            for (int q = 0; q < 4; q++) {
                float i_ = sigmoid_fast(hsum2(acc[0 * 4 + q]));
                float f_ = sigmoid_fast(hsum2(acc[1 * 4 + q]));
                float g_ = tanh_fast(hsum2(acc[2 * 4 + q]));
                float o_ = sigmoid_fast(hsum2(acc[3 * 4 + q]));
                cst[q] = f_ * cst[q] + i_ * g_;
                h1T[(rq >> 2) * 32 + (bg * 4 + q) * 4 + (rq & 3)] = o_ * tanh_fast(cst[q]);
            }
            bar_sync(7, 128);                    // B-internal: h1T visible for t+1
        }
    }

    __syncthreads();   // final h1 visible to all

    // ===== head: out = relu(h1 @ W1^T + b1) @ W2^T + b2 =====
    {
        const int hb = tid >> 5;    // batch 0..7
        const int hu = tid & 31;    // hidden unit 0..31
        const float* w1r = W1 + hu * HDIM;
        float acc = b1[hu];
#pragma unroll
        for (int k = 0; k < HDIM; k++)
            acc += w1r[k] * h1T[(k >> 2) * 32 + hb * 4 + (k & 3)];
        acc = fmaxf(acc, 0.0f) * W2[hu];
        sW0[hb * 32 + hu] = acc;    // reuse sW0 as scratch
    }
    __syncthreads();
    if (tid < NB) {
        float s = b2[0];
#pragma unroll
        for (int u = 0; u < 32; u++) s += sW0[tid * 32 + u];
        out[bbase + tid] = s;
    }
}

extern "C" void kernel_launch(void* const* d_in, const int* in_sizes, int n_in,
                              void* d_out, int out_size) {
    (void)in_sizes; (void)n_in; (void)out_size;
    const float* x    = (const float*)d_in[0];
    const float* Wih0 = (const float*)d_in[1];
    const float* Whh0 = (const float*)d_in[2];
    const float* bih0 = (const float*)d_in[3];
    const float* bhh0 = (const float*)d_in[4];
    const float* Wih1 = (const float*)d_in[5];
    const float* Whh1 = (const float*)d_in[6];
    const float* bih1 = (const float*)d_in[7];
    const float* bhh1 = (const float*)d_in[8];
    const float* W1   = (const float*)d_in[9];
    const float* b1   = (const float*)d_in[10];
    const float* W2   = (const float*)d_in[11];
    const float* b2   = (const float*)d_in[12];
    float* out = (float*)d_out;

    const size_t smem_bytes = (size_t)SMEM_FLOATS * sizeof(float);
    cudaFuncSetAttribute(lstm_return_kernel,
                         cudaFuncAttributeMaxDynamicSharedMemorySize,
                         (int)smem_bytes);
    lstm_return_kernel<<<BATCH / NB, NTHR, smem_bytes>>>(
        x, Wih0, Whh0, bih0, bhh0, Wih1, Whh1, bih1, bhh1,
        W1, b1, W2, b2, out);
}

// round 14
// speedup vs baseline: 1.1317x; 1.1317x over previous
#include <cuda_runtime.h>
#include <cuda_bf16.h>
#include <cstdint>

#define T_SEQ 512
#define BATCH 1024
#define DIN   32
#define HDIM  64
#define G     256     // 4*H gate rows
#define NB    8       // batches per CTA
#define NTHR  256     // A: warps 0-3 (layer 0 + x-part), B: warps 4-7 (layer 1)
#define SW0_S 68      // Whh0 row stride: 68%32=4 -> 2-wf LDS.128 at 16 distinct rows
#define SW1_S 132     // [Wih1|Whh1] row stride: 132%32=4 -> same
#define XP_S  9       // x-part exchange stride: coprime 32 -> conflict-free

// smem floats: sW0 17408 | sW1 33792 | xp 2*2304 | xsb 2*256 | h0T 1024 | h1T 512
//            = 57856 fl = 231424 B  (<= 232448 B cap)
#define SMEM_FLOATS (G*SW0_S + G*SW1_S + 2*(G*XP_S) + 2*(NB*DIN) + 2*(NB*64) + NB*64)

__device__ __forceinline__ unsigned long long pack2(float lo, float hi) {
    unsigned long long r;
    asm("mov.b64 %0, {%1,%2};" : "=l"(r) : "f"(lo), "f"(hi));
    return r;
}
__device__ __forceinline__ void fma2(unsigned long long& d,
                                     unsigned long long a, unsigned long long b) {
    asm("fma.rn.f32x2 %0, %1, %2, %0;" : "+l"(d) : "l"(a), "l"(b));
}
__device__ __forceinline__ float hsum2(unsigned long long v) {
    float lo, hi;
    asm("mov.b64 {%0,%1}, %2;" : "=f"(lo), "=f"(hi) : "l"(v));
    return lo + hi;
}
__device__ __forceinline__ float sigmoid_fast(float x) {
    return __fdividef(1.0f, 1.0f + __expf(-x));
}
__device__ __forceinline__ float tanh_fast(float x) {
    return 1.0f - __fdividef(2.0f, __expf(2.0f * x) + 1.0f);
}
__device__ __forceinline__ void bar_sync(int id, int cnt) {
    asm volatile("bar.sync %0, %1;" :: "r"(id), "r"(cnt) : "memory");
}
__device__ __forceinline__ void bar_arrive(int id, int cnt) {
    asm volatile("bar.arrive %0, %1;" :: "r"(id), "r"(cnt) : "memory");
}

extern __shared__ float smem[];

__global__ void __launch_bounds__(NTHR, 1)
lstm_return_kernel(const float* __restrict__ x,
                   const float* __restrict__ Wih0, const float* __restrict__ Whh0,
                   const float* __restrict__ bih0, const float* __restrict__ bhh0,
                   const float* __restrict__ Wih1, const float* __restrict__ Whh1,
                   const float* __restrict__ bih1, const float* __restrict__ bhh1,
                   const float* __restrict__ W1,   const float* __restrict__ b1,
                   const float* __restrict__ W2,   const float* __restrict__ b2,
                   float* __restrict__ out)
{
    float* sW0 = smem;                 // [256][68]  Whh0
    float* sW1 = sW0 + G * SW0_S;      // [256][132] [Wih1|Whh1]
    float* xp  = sW1 + G * SW1_S;      // [2][256][9] x-part (incl. bias0), dbl-buf
    float* xsb = xp  + 2 * G * XP_S;   // [2][8][32]  x staging, dbl-buf
    float* h0T = xsb + 2 * NB * DIN;   // [2][16][8][4] h0 transposed, dbl-buf
    float* h1T = h0T + 2 * 512;        // [16][8][4]    h1 transposed

    const int tid   = threadIdx.x;
    const int l     = tid & 31;
    const bool grpA = (tid < 128);
    const int gw    = (tid >> 5) & 3;       // warp index within group
    const int rq    = gw * 16 + (l & 15);   // owned unit (rows rq+64m, m=0..3)
    const int bg    = l >> 4;               // batch half
    const int bbase = blockIdx.x * NB;

    // ---- stage weights ----
    for (int i = tid; i < G * HDIM; i += NTHR) {
        int r = i >> 6, c = i & 63;
        sW0[r * SW0_S + c]        = Whh0[i];
        sW1[r * SW1_S + c]        = Wih1[i];
        sW1[r * SW1_S + HDIM + c] = Whh1[i];
    }
    for (int i = tid; i < 3 * 512; i += NTHR) h0T[i] = 0.0f;   // h0T + h1T

    // ---- A: Wih0 row-pair (jx, jx+128) in registers, packed f32x2 ----
    const int jx = tid;   // valid for grpA (tid<128)
    unsigned long long wx0[16], wx1[16];
#pragma unroll
    for (int k = 0; k < 16; k++) {
        int r0 = jx * DIN + 2 * k, r1 = (jx + 128) * DIN + 2 * k;
        wx0[k] = grpA ? pack2(Wih0[r0], Wih0[r0 + 1]) : 0ull;
        wx1[k] = grpA ? pack2(Wih0[r1], Wih0[r1 + 1]) : 0ull;
    }
    float bxa = 0.f, bxb = 0.f;
    if (grpA) { bxa = bih0[jx] + bhh0[jx]; bxb = bih0[jx + 128] + bhh0[jx + 128]; }

    float bs1[4];
#pragma unroll
    for (int m = 0; m < 4; m++)
        bs1[m] = grpA ? 0.0f : (bih1[rq + 64 * m] + bhh1[rq + 64 * m]);

    float cst[4] = {0.f, 0.f, 0.f, 0.f};

    // x staging (A): thread -> (batch xb, channels xc, xc+1)
    const int xb = tid >> 4, xc = (tid & 15) * 2;
    const float* xptr = x + ((size_t)(bbase + (xb & 7)) * T_SEQ) * DIN + xc;
    float2 xcur = make_float2(0.f, 0.f);
    if (grpA) {
        *(float2*)(xsb + 0 * 256 + xb * DIN + xc) = *(const float2*)(xptr);        // x(0)
        *(float2*)(xsb + 1 * 256 + xb * DIN + xc) = *(const float2*)(xptr + DIN);  // x(1)
        xcur = *(const float2*)(xptr + 2 * DIN);                                   // x(2)
    }

    const int wr0 = rq * SW0_S, wr1 = rq * SW1_S;

    __syncthreads();   // weights, zeros, xsb visible

    if (grpA) {
        // helper: compute x-part for buffer `buf` (reads xsb[buf], writes xp[buf])
        auto xpart = [&](int buf) {
            const float* xsp = xsb + buf * 256;
            float* xpd = xp + buf * (G * XP_S);
            unsigned long long a0[NB], a1[NB];
#pragma unroll
            for (int b = 0; b < NB; b++) { a0[b] = pack2(bxa, 0.f); a1[b] = pack2(bxb, 0.f); }
#pragma unroll
            for (int kc = 0; kc < 8; kc++) {
                const unsigned long long u0 = wx0[2*kc], u1 = wx0[2*kc+1];
                const unsigned long long v0 = wx1[2*kc], v1 = wx1[2*kc+1];
#pragma unroll
                for (int b = 0; b < NB; b++) {
                    ulonglong2 iv = *(const ulonglong2*)(xsp + b * DIN + 4 * kc);
                    fma2(a0[b], u0, iv.x); fma2(a0[b], u1, iv.y);
                    fma2(a1[b], v0, iv.x); fma2(a1[b], v1, iv.y);
                }
            }
#pragma unroll
            for (int b = 0; b < NB; b++) {
                xpd[jx * XP_S + b]         = hsum2(a0[b]);
                xpd[(jx + 128) * XP_S + b] = hsum2(a1[b]);
            }
        };

        xpart(0);                 // xp[0] = x-part(t=0)
        bar_sync(5, 128);         // xp[0] visible within A

        // =========================== GROUP A: layer 0 ===========================
        for (int t = 0; t < T_SEQ; t++) {
            const int p = t & 1;
            // ---- quad GEMV(t): acc init from xp[p], h0(t-1) from h0T[p^1] ----
            const float* xpc = xp + p * (G * XP_S);
            unsigned long long acc[16];
#pragma unroll
            for (int m = 0; m < 4; m++)
#pragma unroll
                for (int q = 0; q < 4; q++)
                    acc[m * 4 + q] = pack2(xpc[(rq + 64 * m) * XP_S + bg * 4 + q], 0.f);
            const float* h0p = h0T + (p ^ 1) * 512;
#pragma unroll
            for (int kc = 0; kc < 16; kc++) {
                ulonglong2 wv0 = *(const ulonglong2*)(sW0 + wr0 +   0 * SW0_S + 4 * kc);
                ulonglong2 wv1 = *(const ulonglong2*)(sW0 + wr0 +  64 * SW0_S + 4 * kc);
                ulonglong2 wv2 = *(const ulonglong2*)(sW0 + wr0 + 128 * SW0_S + 4 * kc);
                ulonglong2 wv3 = *(const ulonglong2*)(sW0 + wr0 + 192 * SW0_S + 4 * kc);
#pragma unroll
                for (int q = 0; q < 4; q++) {
                    ulonglong2 iv = *(const ulonglong2*)(h0p + kc * 32 + (bg * 4 + q) * 4);
                    fma2(acc[0 * 4 + q], wv0.x, iv.x); fma2(acc[0 * 4 + q], wv0.y, iv.y);
                    fma2(acc[1 * 4 + q], wv1.x, iv.x); fma2(acc[1 * 4 + q], wv1.y, iv.y);
                    fma2(acc[2 * 4 + q], wv2.x, iv.x); fma2(acc[2 * 4 + q], wv2.y, iv.y);
                    fma2(acc[3 * 4 + q], wv3.x, iv.x); fma2(acc[3 * 4 + q], wv3.y, iv.y);
                }
            }
            if (t >= 2) bar_sync(3 + p, NTHR);   // h0T[p] free (B consumed t-2)
            // ---- activations + cell + h0 write ----
            float* h0c = h0T + p * 512;
#pragma unroll
            for (int q = 0; q < 4; q++) {
                float i_ = sigmoid_fast(hsum2(acc[0 * 4 + q]));
                float f_ = sigmoid_fast(hsum2(acc[1 * 4 + q]));
                float g_ = tanh_fast(hsum2(acc[2 * 4 + q]));
                float o_ = sigmoid_fast(hsum2(acc[3 * 4 + q]));
                cst[q] = f_ * cst[q] + i_ * g_;
                float h = o_ * tanh_fast(cst[q]);
                h0c[(rq >> 2) * 32 + (bg * 4 + q) * 4 + (rq & 3)] = h;
            }
            bar_arrive(1 + p, NTHR);             // h0(t) ready for B

            // stage x(t+2) into xsb[p] (its last reader was xpart at t-1, sealed by bar 5)
            if (t + 2 < T_SEQ) {
                *(float2*)(xsb + p * 256 + xb * DIN + xc) = xcur;
                if (t + 3 < T_SEQ) xcur = *(const float2*)(xptr + (size_t)(t + 3) * DIN);
            }
            // x-part for step t+1 from xsb[p^1] -> xp[p^1]
            if (t + 1 < T_SEQ) xpart(p ^ 1);
            bar_sync(5, 128);                    // xp, xsb, h0T[p] visible within A
        }
    } else {
        // =========================== GROUP B: layer 1 (R12 structure) ===========================
        for (int t = 0; t < T_SEQ; t++) {
            const int p = t & 1;
            bar_sync(1 + p, NTHR);               // wait h0(t); orders h1T too
            const float* h0p = h0T + p * 512;

            unsigned long long acc[16];
#pragma unroll
            for (int m = 0; m < 4; m++)
#pragma unroll
                for (int q = 0; q < 4; q++) acc[m * 4 + q] = pack2(bs1[m], 0.0f);
            // part 1: h0 @ Wih1^T
#pragma unroll
            for (int kc = 0; kc < 16; kc++) {
                ulonglong2 wv0 = *(const ulonglong2*)(sW1 + wr1 +   0 * SW1_S + 4 * kc);
                ulonglong2 wv1 = *(const ulonglong2*)(sW1 + wr1 +  64 * SW1_S + 4 * kc);
                ulonglong2 wv2 = *(const ulonglong2*)(sW1 + wr1 + 128 * SW1_S + 4 * kc);
                ulonglong2 wv3 = *(const ulonglong2*)(sW1 + wr1 + 192 * SW1_S + 4 * kc);
#pragma unroll
                for (int q = 0; q < 4; q++) {
                    ulonglong2 iv = *(const ulonglong2*)(h0p + kc * 32 + (bg * 4 + q) * 4);
                    fma2(acc[0 * 4 + q], wv0.x, iv.x); fma2(acc[0 * 4 + q], wv0.y, iv.y);
                    fma2(acc[1 * 4 + q], wv1.x, iv.x); fma2(acc[1 * 4 + q], wv1.y, iv.y);
                    fma2(acc[2 * 4 + q], wv2.x, iv.x); fma2(acc[2 * 4 + q], wv2.y, iv.y);
                    fma2(acc[3 * 4 + q], wv3.x, iv.x); fma2(acc[3 * 4 + q], wv3.y, iv.y);
                }
            }
            bar_arrive(3 + p, NTHR);             // h0T[p] consumed
            // part 2: h1 @ Whh1^T
#pragma unroll
            for (int kc = 0; kc < 16; kc++) {
                ulonglong2 wv0 = *(const ulonglong2*)(sW1 + wr1 +   0 * SW1_S + 64 + 4 * kc);
                ulonglong2 wv1 = *(const ulonglong2*)(sW1 + wr1 +  64 * SW1_S + 64 + 4 * kc);
                ulonglong2 wv2 = *(const ulonglong2*)(sW1 + wr1 + 128 * SW1_S + 64 + 4 * kc);
                ulonglong2 wv3 = *(const ulonglong2*)(sW1 + wr1 + 192 * SW1_S + 64 + 4 * kc);
#pragma unroll
                for (int q = 0; q < 4; q++) {
                    ulonglong2 iv = *(const ulonglong2*)(h1T + kc * 32 + (bg * 4 + q) * 4);
                    fma2(acc[0 * 4 + q], wv0.x, iv.x); fma2(acc[0 * 4 + q], wv0.y, iv.y);
                    fma2(acc[1 * 4 + q], wv1.x, iv.x); fma2(acc[1 * 4 + q], wv1.y, iv.y);
                    fma2(acc[2 * 4 + q], wv2.x, iv.x); fma2(acc[2 * 4 + q], wv2.y, iv.y);
                    fma2(acc[3 * 4 + q], wv3.x, iv.x); fma2(acc[3 * 4 + q], wv3.y, iv.y);
                }
            }
#pragma unroll
            for (int q = 0; q < 4; q++) {
                float i_ = sigmoid_fast(hsum2(acc[0 * 4 + q]));
                float f_ = sigmoid_fast(hsum2(acc[1 * 4 + q]));
                float g_ = tanh_fast(hsum2(acc[2 * 4 + q]));
                float o_ = sigmoid_fast(hsum2(acc[3 * 4 + q]));
                cst[q] = f_ * cst[q] + i_ * g_;
                h1T[(rq >> 2) * 32 + (bg * 4 + q) * 4 + (rq & 3)] = o_ * tanh_fast(cst[q]);
            }
            // h1T write->read for t+1 ordered by bar_sync(1+p') full-CTA rendezvous
        }
    }

    __syncthreads();   // final h1 visible to all

    // ===== head: out = relu(h1 @ W1^T + b1) @ W2^T + b2 =====
    {
        const int hb = tid >> 5;    // batch 0..7
        const int hu = tid & 31;    // hidden unit 0..31
        const float* w1r = W1 + hu * HDIM;
        float acc = b1[hu];
#pragma unroll
        for (int k = 0; k < HDIM; k++)
            acc += w1r[k] * h1T[(k >> 2) * 32 + hb * 4 + (k & 3)];
        acc = fmaxf(acc, 0.0f) * W2[hu];
        sW0[hb * 32 + hu] = acc;    // reuse sW0 as scratch
    }
    __syncthreads();
    if (tid < NB) {
        float s = b2[0];
#pragma unroll
        for (int u = 0; u < 32; u++) s += sW0[tid * 32 + u];
        out[bbase + tid] = s;
    }
}

extern "C" void kernel_launch(void* const* d_in, const int* in_sizes, int n_in,
                              void* d_out, int out_size) {
    (void)in_sizes; (void)n_in; (void)out_size;
    const float* x    = (const float*)d_in[0];
    const float* Wih0 = (const float*)d_in[1];
    const float* Whh0 = (const float*)d_in[2];
    const float* bih0 = (const float*)d_in[3];
    const float* bhh0 = (const float*)d_in[4];
    const float* Wih1 = (const float*)d_in[5];
    const float* Whh1 = (const float*)d_in[6];
    const float* bih1 = (const float*)d_in[7];
    const float* bhh1 = (const float*)d_in[8];
    const float* W1   = (const float*)d_in[9];
    const float* b1   = (const float*)d_in[10];
    const float* W2   = (const float*)d_in[11];
    const float* b2   = (const float*)d_in[12];
    float* out = (float*)d_out;

    const size_t smem_bytes = (size_t)SMEM_FLOATS * sizeof(float);
    cudaFuncSetAttribute(lstm_return_kernel,
                         cudaFuncAttributeMaxDynamicSharedMemorySize,
                         (int)smem_bytes);
    lstm_return_kernel<<<BATCH / NB, NTHR, smem_bytes>>>(
        x, Wih0, Whh0, bih0, bhh0, Wih1, Whh1, bih1, bhh1,
        W1, b1, W2, b2, out);
}